// round 10
// baseline (speedup 1.0000x reference)
#include <cuda_runtime.h>
#include <cuda_bf16.h>
#include <cstdint>

// Problem constants
#define TT   512      // seq len
#define HH   128      // hidden
#define BB   2048     // batch
#define NB   16       // batch per CTA
#define NW   8        // warps per CTA
#define NTH  (NW*32)  // 256 threads
#define NCTA (BB/NB)  // 128 CTAs
#define KPAD 136      // hbuf row stride in bf16 elems (128 + 8 pad)

// SMEM layout (bytes)
#define SM_XS   0                          // x transposed [T][NB] f32 : 32768
#define SM_H0   32768                      // h buffer A [NB][KPAD] bf16 : 4352 -> 4608
#define SM_H1   (SM_H0 + 4608)             // h buffer B
#define SM_RED  (SM_H1 + 4608)             // per-warp MLP partials: NW*NB f32 = 512
#define SM_TOTAL (SM_RED + 512)            // 42496

__device__ __forceinline__ float tanhap(float x) {
    float y; asm("tanh.approx.f32 %0, %1;" : "=f"(y) : "f"(x)); return y;
}
__device__ __forceinline__ float sigap(float x) {
    return fmaf(0.5f, tanhap(0.5f * x), 0.5f);
}
__device__ __forceinline__ uint32_t packbf(float lo, float hi) {
    __nv_bfloat162 v = __floats2bfloat162_rn(lo, hi);
    return *reinterpret_cast<uint32_t*>(&v);
}
__device__ __forceinline__ void mma16816(
    float& d0, float& d1, float& d2, float& d3,
    uint32_t a0, uint32_t a1, uint32_t a2, uint32_t a3,
    uint32_t b0, uint32_t b1)
{
    asm volatile(
        "mma.sync.aligned.m16n8k16.row.col.f32.bf16.bf16.f32 "
        "{%0,%1,%2,%3}, {%4,%5,%6,%7}, {%8,%9}, {%0,%1,%2,%3};"
        : "+f"(d0), "+f"(d1), "+f"(d2), "+f"(d3)
        : "r"(a0), "r"(a1), "r"(a2), "r"(a3), "r"(b0), "r"(b1));
}

__global__ void __launch_bounds__(NTH, 1) lstm_hmma_kernel(
    const float* __restrict__ x,    const float* __restrict__ hx0,
    const float* __restrict__ cx0,  const float* __restrict__ Wih,
    const float* __restrict__ Whh,  const float* __restrict__ bih,
    const float* __restrict__ bhh,  const float* __restrict__ Wmlp,
    const float* __restrict__ bmlp, float* __restrict__ out)
{
    extern __shared__ char smem[];
    const int tid  = threadIdx.x;
    const int w    = tid >> 5;          // warp id: owns hid [16w, 16w+16)
    const int l    = tid & 31;
    const int b0   = blockIdx.x * NB;
    const int lq   = l >> 2;            // 0..7
    const int lr   = l & 3;             // 0..3

    // ---------- stage x transposed: xs[t][n] ----------
    float* xs = (float*)(smem + SM_XS);
    for (int idx = tid; idx < NB * TT; idx += NTH) {
        int n = idx >> 9, t = idx & (TT - 1);
        xs[t * NB + n] = x[(size_t)(b0 + n) * TT + t];   // coalesced over t
    }
    // ---------- stage h0 into hbuf0[n][k] ----------
    __nv_bfloat16* hb0 = (__nv_bfloat16*)(smem + SM_H0);
    for (int idx = tid; idx < NB * HH; idx += NTH) {
        int n = idx >> 7, k = idx & 127;
        hb0[n * KPAD + k] = __float2bfloat16(hx0[(size_t)(b0 + n) * HH + k]);
    }

    // ---------- load W_hh A-fragments into registers (constant over t) ----------
    // Fragment (m16n8k16 row-major A), gate g, k-chunk kc:
    //   rows: r0 = g*128 + 16w + lq, r1 = r0 + 8
    //   cols: c0 = 16kc + 2lr  -> a0={r0:c0,c0+1} a1={r1:...} a2={r0:c0+8,+9} a3={r1:...}
    uint32_t Afr[4][8][4];
#pragma unroll
    for (int g = 0; g < 4; g++) {
        const int r0 = g * 128 + 16 * w + lq;
#pragma unroll
        for (int kc = 0; kc < 8; kc++) {
            const int c0 = kc * 16 + 2 * lr;
            const float* p0 = Whh + (size_t)r0 * HH + c0;
            const float* p1 = Whh + (size_t)(r0 + 8) * HH + c0;
            Afr[g][kc][0] = packbf(p0[0], p0[1]);
            Afr[g][kc][1] = packbf(p1[0], p1[1]);
            Afr[g][kc][2] = packbf(p0[8], p0[9]);
            Afr[g][kc][3] = packbf(p1[8], p1[9]);
        }
    }

    // ---------- per-thread gate constants (2 hid rows: lq and lq+8) ----------
    float wg4[2][4], bg4[2][4], pm[2];
#pragma unroll
    for (int r = 0; r < 2; r++) {
        const int hid = 16 * w + lq + 8 * r;
#pragma unroll
        for (int g = 0; g < 4; g++) {
            wg4[r][g] = Wih[g * 128 + hid];
            bg4[r][g] = bih[g * 128 + hid] + bhh[g * 128 + hid];
        }
        pm[r] = Wmlp[hid];
    }

    // ---------- c state: 8 positions (r, nt, cc) ----------
    // position: hid = 16w + lq + 8r ; n = 8nt + 2lr + cc
    float cst[2][2][2], hsv[2][2][2];
#pragma unroll
    for (int r = 0; r < 2; r++)
#pragma unroll
        for (int nt = 0; nt < 2; nt++)
#pragma unroll
            for (int cc = 0; cc < 2; cc++) {
                int hid = 16 * w + lq + 8 * r;
                int n = 8 * nt + 2 * lr + cc;
                cst[r][nt][cc] = cx0[(size_t)(b0 + n) * HH + hid];
            }

    __syncthreads();

    // ================= main recurrence =================
    uint32_t cur = SM_H0, nxt = SM_H1;
#pragma unroll 1
    for (int t = 0; t < TT; t++) {
        // zero accumulators: acc[gate][ntile][4]
        float acc[4][2][4];
#pragma unroll
        for (int g = 0; g < 4; g++)
#pragma unroll
            for (int nt = 0; nt < 2; nt++)
#pragma unroll
                for (int j = 0; j < 4; j++) acc[g][nt][j] = 0.0f;

        // MMA over K: B frags from hbuf[cur] (conflict-free LDS.b32 pairs)
        const char* hbc = smem + cur;
#pragma unroll
        for (int kc = 0; kc < 8; kc++) {
            const int k0 = kc * 16 + 2 * lr;
            uint32_t b00, b01, b10, b11;
            {
                const int n0 = lq;          // ntile 0: n = lq
                const int n1 = 8 + lq;      // ntile 1
                b00 = *(const uint32_t*)(hbc + (n0 * KPAD + k0) * 2);
                b01 = *(const uint32_t*)(hbc + (n0 * KPAD + k0 + 8) * 2);
                b10 = *(const uint32_t*)(hbc + (n1 * KPAD + k0) * 2);
                b11 = *(const uint32_t*)(hbc + (n1 * KPAD + k0 + 8) * 2);
            }
#pragma unroll
            for (int g = 0; g < 4; g++) {
                mma16816(acc[g][0][0], acc[g][0][1], acc[g][0][2], acc[g][0][3],
                         Afr[g][kc][0], Afr[g][kc][1], Afr[g][kc][2], Afr[g][kc][3],
                         b00, b01);
                mma16816(acc[g][1][0], acc[g][1][1], acc[g][1][2], acc[g][1][3],
                         Afr[g][kc][0], Afr[g][kc][1], Afr[g][kc][2], Afr[g][kc][3],
                         b10, b11);
            }
        }

        // epilogue: gate nonlinearities + state update + store h(t+1)
        const float* xsp = xs + t * NB;
        char* hbn = smem + nxt;
#pragma unroll
        for (int r = 0; r < 2; r++) {
            const int hid = 16 * w + lq + 8 * r;
#pragma unroll
            for (int nt = 0; nt < 2; nt++) {
#pragma unroll
                for (int cc = 0; cc < 2; cc++) {
                    const int j = 2 * r + cc;          // accum reg index for (row r, col cc)
                    const int n = 8 * nt + 2 * lr + cc;
                    const float xv = xsp[n];
                    float gi = acc[0][nt][j] + fmaf(xv, wg4[r][0], bg4[r][0]);
                    float gf = acc[1][nt][j] + fmaf(xv, wg4[r][1], bg4[r][1]);
                    float gg = acc[2][nt][j] + fmaf(xv, wg4[r][2], bg4[r][2]);
                    float go = acc[3][nt][j] + fmaf(xv, wg4[r][3], bg4[r][3]);
                    float ii = sigap(gi), ff = sigap(gf);
                    float g2 = tanhap(gg), oo = sigap(go);
                    float c = fmaf(ff, cst[r][nt][cc], ii * g2);
                    cst[r][nt][cc] = c;
                    float h = oo * tanhap(c);
                    hsv[r][nt][cc] = h;
                    *(__nv_bfloat16*)(hbn + (n * KPAD + hid) * 2) = __float2bfloat16(h);
                }
            }
        }
        __syncthreads();
        uint32_t tmp = cur; cur = nxt; nxt = tmp;
    }

    // ================= final MLP + sigmoid =================
    // partial per thread: sum over its 2 hid rows, keyed by n = 8nt+2lr+cc
    float* red = (float*)(smem + SM_RED);
#pragma unroll
    for (int nt = 0; nt < 2; nt++) {
#pragma unroll
        for (int cc = 0; cc < 2; cc++) {
            float v = fmaf(hsv[0][nt][cc], pm[0], hsv[1][nt][cc] * pm[1]);
            // reduce over the 8 lanes sharing this n (lane bits 2..4)
            v += __shfl_xor_sync(0xffffffffu, v, 4);
            v += __shfl_xor_sync(0xffffffffu, v, 8);
            v += __shfl_xor_sync(0xffffffffu, v, 16);
            if (lq == 0) red[w * NB + 8 * nt + 2 * lr + cc] = v;
        }
    }
    __syncthreads();
    if (tid < NB) {
        float logit = bmlp[0];
#pragma unroll
        for (int wq = 0; wq < NW; wq++) logit += red[wq * NB + tid];
        out[b0 + tid] = 1.0f / (1.0f + __expf(-logit));
    }
}

extern "C" void kernel_launch(void* const* d_in, const int* in_sizes, int n_in,
                              void* d_out, int out_size) {
    (void)in_sizes; (void)n_in; (void)out_size;
    const float* x    = (const float*)d_in[0];
    const float* hx0  = (const float*)d_in[1];
    const float* cx0  = (const float*)d_in[2];
    const float* Wih  = (const float*)d_in[3];
    const float* Whh  = (const float*)d_in[4];
    const float* bih  = (const float*)d_in[5];
    const float* bhh  = (const float*)d_in[6];
    const float* Wmlp = (const float*)d_in[7];
    const float* bmlp = (const float*)d_in[8];
    float* out = (float*)d_out;

    cudaFuncSetAttribute(lstm_hmma_kernel,
                         cudaFuncAttributeMaxDynamicSharedMemorySize, SM_TOTAL);
    lstm_hmma_kernel<<<NCTA, NTH, SM_TOTAL>>>(
        x, hx0, cx0, Wih, Whh, bih, bhh, Wmlp, bmlp, out);
}

// round 12
// speedup vs baseline: 1.3924x; 1.3924x over previous
#include <cuda_runtime.h>
#include <cuda_bf16.h>
#include <cstdint>

// Problem constants
#define TT   512      // seq len
#define HH   128      // hidden
#define BB   2048     // batch
#define NB   16       // batch per CTA (split into halves of 8)
#define NW   8        // warps per CTA
#define NTH  (NW*32)  // 256 threads
#define NCTA (BB/NB)  // 128 CTAs
#define KPAD 136      // h-buffer row stride in bf16 elems (128 + 8 pad)

// SMEM layout (bytes)
#define SM_XS   0                          // x transposed [T][NB] f32 : 32768
#define SM_HA   32768                      // h half A [8][KPAD] bf16 : 2176 -> 2304
#define SM_HB   (SM_HA + 2304)             // h half B
#define SM_RED  (SM_HB + 2304)             // per-warp MLP partials: NW*NB f32 = 512
#define SM_TOTAL (SM_RED + 512)

__device__ __forceinline__ float tanhap(float x) {
    float y; asm("tanh.approx.f32 %0, %1;" : "=f"(y) : "f"(x)); return y;
}
__device__ __forceinline__ float sigap(float x) {
    return fmaf(0.5f, tanhap(0.5f * x), 0.5f);
}
__device__ __forceinline__ uint32_t packbf(float lo, float hi) {
    __nv_bfloat162 v = __floats2bfloat162_rn(lo, hi);
    return *reinterpret_cast<uint32_t*>(&v);
}
__device__ __forceinline__ void mma16816(
    float& d0, float& d1, float& d2, float& d3,
    uint32_t a0, uint32_t a1, uint32_t a2, uint32_t a3,
    uint32_t b0, uint32_t b1)
{
    asm volatile(
        "mma.sync.aligned.m16n8k16.row.col.f32.bf16.bf16.f32 "
        "{%0,%1,%2,%3}, {%4,%5,%6,%7}, {%8,%9}, {%0,%1,%2,%3};"
        : "+f"(d0), "+f"(d1), "+f"(d2), "+f"(d3)
        : "r"(a0), "r"(a1), "r"(a2), "r"(a3), "r"(b0), "r"(b1));
}

// One n8 half: gates[4 gates x 16 hid][8 batch] accumulated into acc[g][4].
__device__ __forceinline__ void mma_half(
    const char* __restrict__ hb, const uint32_t (&Afr)[4][8][4],
    float (&acc)[4][4], int lq, int lr)
{
#pragma unroll
    for (int g = 0; g < 4; g++)
#pragma unroll
        for (int j = 0; j < 4; j++) acc[g][j] = 0.0f;
#pragma unroll
    for (int kc = 0; kc < 8; kc++) {
        const int k0 = kc * 16 + 2 * lr;
        uint32_t b0 = *(const uint32_t*)(hb + (lq * KPAD + k0) * 2);
        uint32_t b1 = *(const uint32_t*)(hb + (lq * KPAD + k0 + 8) * 2);
#pragma unroll
        for (int g = 0; g < 4; g++)
            mma16816(acc[g][0], acc[g][1], acc[g][2], acc[g][3],
                     Afr[g][kc][0], Afr[g][kc][1], Afr[g][kc][2], Afr[g][kc][3],
                     b0, b1);
    }
}

// Epilogue for one half: nonlinearities + c/h update + h store into hb.
// Position (r, cc): hid = 16w + lq + 8r ; local n = 2lr + cc ; acc reg j = 2r+cc.
__device__ __forceinline__ void epi_half(
    const float (&acc)[4][4], float (&cst)[2][2], float (&hsv)[2][2],
    const float* __restrict__ xsp, char* __restrict__ hb,
    const float (&wg4)[2][4], const float (&bg4)[2][4],
    int w, int lq, int lr)
{
#pragma unroll
    for (int cc = 0; cc < 2; cc++) {
        const int nl = 2 * lr + cc;
        const float xv = xsp[nl];
#pragma unroll
        for (int r = 0; r < 2; r++) {
            const int j = 2 * r + cc;
            float gi = acc[0][j] + fmaf(xv, wg4[r][0], bg4[r][0]);
            float gf = acc[1][j] + fmaf(xv, wg4[r][1], bg4[r][1]);
            float gg = acc[2][j] + fmaf(xv, wg4[r][2], bg4[r][2]);
            float go = acc[3][j] + fmaf(xv, wg4[r][3], bg4[r][3]);
            float ii = sigap(gi), ff = sigap(gf);
            float g2 = tanhap(gg), oo = sigap(go);
            float c = fmaf(ff, cst[r][cc], ii * g2);
            cst[r][cc] = c;
            float h = oo * tanhap(c);
            hsv[r][cc] = h;
            const int hid = 16 * w + lq + 8 * r;
            *(__nv_bfloat16*)(hb + (nl * KPAD + hid) * 2) = __float2bfloat16(h);
        }
    }
}

__global__ void __launch_bounds__(NTH, 1) lstm_hmma_kernel(
    const float* __restrict__ x,    const float* __restrict__ hx0,
    const float* __restrict__ cx0,  const float* __restrict__ Wih,
    const float* __restrict__ Whh,  const float* __restrict__ bih,
    const float* __restrict__ bhh,  const float* __restrict__ Wmlp,
    const float* __restrict__ bmlp, float* __restrict__ out)
{
    extern __shared__ char smem[];
    const int tid  = threadIdx.x;
    const int w    = tid >> 5;          // warp owns hid [16w, 16w+16)
    const int l    = tid & 31;
    const int b0   = blockIdx.x * NB;
    const int lq   = l >> 2;            // 0..7
    const int lr   = l & 3;             // 0..3

    // ---------- stage x transposed: xs[t][n] ----------
    float* xs = (float*)(smem + SM_XS);
    for (int idx = tid; idx < NB * TT; idx += NTH) {
        int n = idx >> 9, t = idx & (TT - 1);
        xs[t * NB + n] = x[(size_t)(b0 + n) * TT + t];
    }
    // ---------- stage h0: half A rows n 0..7, half B rows n 8..15 ----------
    for (int idx = tid; idx < NB * HH; idx += NTH) {
        int n = idx >> 7, k = idx & 127;
        char* hb = smem + ((n < 8) ? SM_HA : SM_HB);
        ((__nv_bfloat16*)hb)[(n & 7) * KPAD + k] =
            __float2bfloat16(hx0[(size_t)(b0 + n) * HH + k]);
    }

    // ---------- W_hh A-fragments in registers (constant over t) ----------
    uint32_t Afr[4][8][4];
#pragma unroll
    for (int g = 0; g < 4; g++) {
        const int r0 = g * 128 + 16 * w + lq;
#pragma unroll
        for (int kc = 0; kc < 8; kc++) {
            const int c0 = kc * 16 + 2 * lr;
            const float* p0 = Whh + (size_t)r0 * HH + c0;
            const float* p1 = Whh + (size_t)(r0 + 8) * HH + c0;
            Afr[g][kc][0] = packbf(p0[0], p0[1]);
            Afr[g][kc][1] = packbf(p1[0], p1[1]);
            Afr[g][kc][2] = packbf(p0[8], p0[9]);
            Afr[g][kc][3] = packbf(p1[8], p1[9]);
        }
    }

    // ---------- per-thread gate constants ----------
    float wg4[2][4], bg4[2][4], pm[2];
#pragma unroll
    for (int r = 0; r < 2; r++) {
        const int hid = 16 * w + lq + 8 * r;
#pragma unroll
        for (int g = 0; g < 4; g++) {
            wg4[r][g] = Wih[g * 128 + hid];
            bg4[r][g] = bih[g * 128 + hid] + bhh[g * 128 + hid];
        }
        pm[r] = Wmlp[hid];
    }

    // ---------- c state per half ----------
    float cstA[2][2], cstB[2][2], hsvA[2][2], hsvB[2][2];
#pragma unroll
    for (int r = 0; r < 2; r++)
#pragma unroll
        for (int cc = 0; cc < 2; cc++) {
            const int hid = 16 * w + lq + 8 * r;
            const int nl = 2 * lr + cc;
            cstA[r][cc] = cx0[(size_t)(b0 + nl) * HH + hid];
            cstB[r][cc] = cx0[(size_t)(b0 + 8 + nl) * HH + hid];
        }

    char* hbA = smem + SM_HA;
    char* hbB = smem + SM_HB;
    __syncthreads();

    float accA[4][4], accB[4][4];

    // ---------- software-pipelined recurrence ----------
    // phase1(t): MMA_A(t) || epi_B(t-1)   phase2(t): MMA_B(t) || epi_A(t)
    // t = 0 peeled (no epi_B yet):
    mma_half(hbA, Afr, accA, lq, lr);
    __syncthreads();
    mma_half(hbB, Afr, accB, lq, lr);
    epi_half(accA, cstA, hsvA, xs, hbA, wg4, bg4, w, lq, lr);
    __syncthreads();

#pragma unroll 1
    for (int t = 1; t < TT; t++) {
        // phase1: tensor work for half A overlaps MUFU epilogue of half B
        mma_half(hbA, Afr, accA, lq, lr);
        epi_half(accB, cstB, hsvB, xs + (t - 1) * NB + 8, hbB, wg4, bg4, w, lq, lr);
        __syncthreads();
        // phase2: tensor work for half B overlaps MUFU epilogue of half A
        mma_half(hbB, Afr, accB, lq, lr);
        epi_half(accA, cstA, hsvA, xs + t * NB, hbA, wg4, bg4, w, lq, lr);
        __syncthreads();
    }
    // tail: finish half B at t = TT-1
    epi_half(accB, cstB, hsvB, xs + (TT - 1) * NB + 8, hbB, wg4, bg4, w, lq, lr);

    // ---------- final MLP + sigmoid ----------
    float* red = (float*)(smem + SM_RED);
#pragma unroll
    for (int half = 0; half < 2; half++) {
#pragma unroll
        for (int cc = 0; cc < 2; cc++) {
            float v = half ? fmaf(hsvB[0][cc], pm[0], hsvB[1][cc] * pm[1])
                           : fmaf(hsvA[0][cc], pm[0], hsvA[1][cc] * pm[1]);
            // reduce over the 8 lanes (lq = lane bits 2..4) sharing this n
            v += __shfl_xor_sync(0xffffffffu, v, 4);
            v += __shfl_xor_sync(0xffffffffu, v, 8);
            v += __shfl_xor_sync(0xffffffffu, v, 16);
            if (lq == 0) red[w * NB + 8 * half + 2 * lr + cc] = v;
        }
    }
    __syncthreads();
    if (tid < NB) {
        float logit = bmlp[0];
#pragma unroll
        for (int wq = 0; wq < NW; wq++) logit += red[wq * NB + tid];
        out[b0 + tid] = 1.0f / (1.0f + __expf(-logit));
    }
}

extern "C" void kernel_launch(void* const* d_in, const int* in_sizes, int n_in,
                              void* d_out, int out_size) {
    (void)in_sizes; (void)n_in; (void)out_size;
    const float* x    = (const float*)d_in[0];
    const float* hx0  = (const float*)d_in[1];
    const float* cx0  = (const float*)d_in[2];
    const float* Wih  = (const float*)d_in[3];
    const float* Whh  = (const float*)d_in[4];
    const float* bih  = (const float*)d_in[5];
    const float* bhh  = (const float*)d_in[6];
    const float* Wmlp = (const float*)d_in[7];
    const float* bmlp = (const float*)d_in[8];
    float* out = (float*)d_out;

    cudaFuncSetAttribute(lstm_hmma_kernel,
                         cudaFuncAttributeMaxDynamicSharedMemorySize, SM_TOTAL);
    lstm_hmma_kernel<<<NCTA, NTH, SM_TOTAL>>>(
        x, hx0, cx0, Wih, Whh, bih, bhh, Wmlp, bmlp, out);
}

// round 13
// speedup vs baseline: 1.4778x; 1.0613x over previous
#include <cuda_runtime.h>
#include <cuda_bf16.h>
#include <cstdint>

// Problem constants
#define TT   512      // seq len
#define HH   128      // hidden
#define BB   2048     // batch
#define NB   16       // batch per CTA (split into halves of 8)
#define NW   8        // warps per CTA
#define NTH  (NW*32)  // 256 threads
#define NCTA (BB/NB)  // 128 CTAs
#define KPAD 136      // h-buffer row stride in bf16 elems (128 + 8 pad)

// SMEM layout (bytes)
#define SM_XS   0                          // x transposed [T][NB] f32 : 32768
#define SM_HA   32768                      // h half A [8][KPAD] bf16 : 2176 -> 2304
#define SM_HB   (SM_HA + 2304)             // h half B
#define SM_RED  (SM_HB + 2304)             // per-warp MLP partials: NW*NB f32 = 512
#define SM_TOTAL (SM_RED + 512)

__device__ __forceinline__ float tanhap(float x) {
    float y; asm("tanh.approx.f32 %0, %1;" : "=f"(y) : "f"(x)); return y;
}
__device__ __forceinline__ uint32_t packbf(float lo, float hi) {
    __nv_bfloat162 v = __floats2bfloat162_rn(lo, hi);
    return *reinterpret_cast<uint32_t*>(&v);
}
__device__ __forceinline__ void mma16816(
    float& d0, float& d1, float& d2, float& d3,
    uint32_t a0, uint32_t a1, uint32_t a2, uint32_t a3,
    uint32_t b0, uint32_t b1)
{
    asm volatile(
        "mma.sync.aligned.m16n8k16.row.col.f32.bf16.bf16.f32 "
        "{%0,%1,%2,%3}, {%4,%5,%6,%7}, {%8,%9}, {%0,%1,%2,%3};"
        : "+f"(d0), "+f"(d1), "+f"(d2), "+f"(d3)
        : "r"(a0), "r"(a1), "r"(a2), "r"(a3), "r"(b0), "r"(b1));
}

// One n8 half. Accumulators are INITIALIZED with the x*W_ih + bias
// contribution (i/f/o rows pre-scaled by 0.5), then MMA accumulates W_hh @ h.
__device__ __forceinline__ void mma_half(
    const char* __restrict__ hb, const uint32_t (&Afr)[4][8][4],
    float (&acc)[4][4], const float* __restrict__ xsp,
    const float (&wg4)[2][4], const float (&bg4)[2][4],
    int lq, int lr)
{
    const float xv0 = xsp[2 * lr];
    const float xv1 = xsp[2 * lr + 1];
#pragma unroll
    for (int g = 0; g < 4; g++)
#pragma unroll
        for (int r = 0; r < 2; r++) {
            acc[g][2 * r + 0] = fmaf(xv0, wg4[r][g], bg4[r][g]);
            acc[g][2 * r + 1] = fmaf(xv1, wg4[r][g], bg4[r][g]);
        }
#pragma unroll
    for (int kc = 0; kc < 8; kc++) {
        const int k0 = kc * 16 + 2 * lr;
        uint32_t b0 = *(const uint32_t*)(hb + (lq * KPAD + k0) * 2);
        uint32_t b1 = *(const uint32_t*)(hb + (lq * KPAD + k0 + 8) * 2);
#pragma unroll
        for (int g = 0; g < 4; g++)
            mma16816(acc[g][0], acc[g][1], acc[g][2], acc[g][3],
                     Afr[g][kc][0], Afr[g][kc][1], Afr[g][kc][2], Afr[g][kc][3],
                     b0, b1);
    }
}

// Epilogue for one half: gates arrive fully formed (bias+x already inside).
// i/f/o preactivations are pre-scaled by 0.5 -> sigmoid = fma(0.5, tanh, 0.5).
__device__ __forceinline__ void epi_half(
    const float (&acc)[4][4], float (&cst)[2][2], float (&hsv)[2][2],
    char* __restrict__ hb, int w, int lq, int lr)
{
#pragma unroll
    for (int cc = 0; cc < 2; cc++) {
        const int nl = 2 * lr + cc;
#pragma unroll
        for (int r = 0; r < 2; r++) {
            const int j = 2 * r + cc;
            float ii = fmaf(0.5f, tanhap(acc[0][j]), 0.5f);
            float ff = fmaf(0.5f, tanhap(acc[1][j]), 0.5f);
            float g2 = tanhap(acc[2][j]);
            float oo = fmaf(0.5f, tanhap(acc[3][j]), 0.5f);
            float c = fmaf(ff, cst[r][cc], ii * g2);
            cst[r][cc] = c;
            float h = oo * tanhap(c);
            hsv[r][cc] = h;
            const int hid = 16 * w + lq + 8 * r;
            *(__nv_bfloat16*)(hb + (nl * KPAD + hid) * 2) = __float2bfloat16(h);
        }
    }
}

__global__ void __launch_bounds__(NTH, 1) lstm_hmma_kernel(
    const float* __restrict__ x,    const float* __restrict__ hx0,
    const float* __restrict__ cx0,  const float* __restrict__ Wih,
    const float* __restrict__ Whh,  const float* __restrict__ bih,
    const float* __restrict__ bhh,  const float* __restrict__ Wmlp,
    const float* __restrict__ bmlp, float* __restrict__ out)
{
    extern __shared__ char smem[];
    const int tid  = threadIdx.x;
    const int w    = tid >> 5;          // warp owns hid [16w, 16w+16)
    const int l    = tid & 31;
    const int b0   = blockIdx.x * NB;
    const int lq   = l >> 2;            // 0..7
    const int lr   = l & 3;             // 0..3

    // ---------- stage x transposed: xs[t][n] ----------
    float* xs = (float*)(smem + SM_XS);
    for (int idx = tid; idx < NB * TT; idx += NTH) {
        int n = idx >> 9, t = idx & (TT - 1);
        xs[t * NB + n] = x[(size_t)(b0 + n) * TT + t];
    }
    // ---------- stage h0: half A rows n 0..7, half B rows n 8..15 ----------
    for (int idx = tid; idx < NB * HH; idx += NTH) {
        int n = idx >> 7, k = idx & 127;
        char* hb = smem + ((n < 8) ? SM_HA : SM_HB);
        ((__nv_bfloat16*)hb)[(n & 7) * KPAD + k] =
            __float2bfloat16(hx0[(size_t)(b0 + n) * HH + k]);
    }

    // ---------- W_hh A-fragments in registers; i/f/o rows scaled by 0.5 ----------
    uint32_t Afr[4][8][4];
#pragma unroll
    for (int g = 0; g < 4; g++) {
        const float sc = (g == 2) ? 1.0f : 0.5f;   // gate order i,f,g,o
        const int r0 = g * 128 + 16 * w + lq;
#pragma unroll
        for (int kc = 0; kc < 8; kc++) {
            const int c0 = kc * 16 + 2 * lr;
            const float* p0 = Whh + (size_t)r0 * HH + c0;
            const float* p1 = Whh + (size_t)(r0 + 8) * HH + c0;
            Afr[g][kc][0] = packbf(sc * p0[0], sc * p0[1]);
            Afr[g][kc][1] = packbf(sc * p1[0], sc * p1[1]);
            Afr[g][kc][2] = packbf(sc * p0[8], sc * p0[9]);
            Afr[g][kc][3] = packbf(sc * p1[8], sc * p1[9]);
        }
    }

    // ---------- per-thread gate constants (i/f/o scaled by 0.5) ----------
    float wg4[2][4], bg4[2][4], pm[2];
#pragma unroll
    for (int r = 0; r < 2; r++) {
        const int hid = 16 * w + lq + 8 * r;
#pragma unroll
        for (int g = 0; g < 4; g++) {
            const float sc = (g == 2) ? 1.0f : 0.5f;
            wg4[r][g] = sc * Wih[g * 128 + hid];
            bg4[r][g] = sc * (bih[g * 128 + hid] + bhh[g * 128 + hid]);
        }
        pm[r] = Wmlp[hid];
    }

    // ---------- c state per half ----------
    float cstA[2][2], cstB[2][2], hsvA[2][2], hsvB[2][2];
#pragma unroll
    for (int r = 0; r < 2; r++)
#pragma unroll
        for (int cc = 0; cc < 2; cc++) {
            const int hid = 16 * w + lq + 8 * r;
            const int nl = 2 * lr + cc;
            cstA[r][cc] = cx0[(size_t)(b0 + nl) * HH + hid];
            cstB[r][cc] = cx0[(size_t)(b0 + 8 + nl) * HH + hid];
        }

    char* hbA = smem + SM_HA;
    char* hbB = smem + SM_HB;
    __syncthreads();

    float accA[4][4], accB[4][4];

    // ---------- software-pipelined recurrence ----------
    // phase1(t): MMA_A(t) || epi_B(t-1)   phase2(t): MMA_B(t) || epi_A(t)
    mma_half(hbA, Afr, accA, xs, wg4, bg4, lq, lr);
    __syncthreads();
    mma_half(hbB, Afr, accB, xs + 8, wg4, bg4, lq, lr);
    epi_half(accA, cstA, hsvA, hbA, w, lq, lr);
    __syncthreads();

#pragma unroll 1
    for (int t = 1; t < TT; t++) {
        // phase1: tensor work for half A overlaps MUFU epilogue of half B
        mma_half(hbA, Afr, accA, xs + t * NB, wg4, bg4, lq, lr);
        epi_half(accB, cstB, hsvB, hbB, w, lq, lr);
        __syncthreads();
        // phase2: tensor work for half B overlaps MUFU epilogue of half A
        mma_half(hbB, Afr, accB, xs + t * NB + 8, wg4, bg4, lq, lr);
        epi_half(accA, cstA, hsvA, hbA, w, lq, lr);
        __syncthreads();
    }
    // tail: finish half B at t = TT-1
    epi_half(accB, cstB, hsvB, hbB, w, lq, lr);

    // ---------- final MLP + sigmoid ----------
    float* red = (float*)(smem + SM_RED);
#pragma unroll
    for (int half = 0; half < 2; half++) {
#pragma unroll
        for (int cc = 0; cc < 2; cc++) {
            float v = half ? fmaf(hsvB[0][cc], pm[0], hsvB[1][cc] * pm[1])
                           : fmaf(hsvA[0][cc], pm[0], hsvA[1][cc] * pm[1]);
            // reduce over the 8 lanes (lq = lane bits 2..4) sharing this n
            v += __shfl_xor_sync(0xffffffffu, v, 4);
            v += __shfl_xor_sync(0xffffffffu, v, 8);
            v += __shfl_xor_sync(0xffffffffu, v, 16);
            if (lq == 0) red[w * NB + 8 * half + 2 * lr + cc] = v;
        }
    }
    __syncthreads();
    if (tid < NB) {
        float logit = bmlp[0];
#pragma unroll
        for (int wq = 0; wq < NW; wq++) logit += red[wq * NB + tid];
        out[b0 + tid] = 1.0f / (1.0f + __expf(-logit));
    }
}

extern "C" void kernel_launch(void* const* d_in, const int* in_sizes, int n_in,
                              void* d_out, int out_size) {
    (void)in_sizes; (void)n_in; (void)out_size;
    const float* x    = (const float*)d_in[0];
    const float* hx0  = (const float*)d_in[1];
    const float* cx0  = (const float*)d_in[2];
    const float* Wih  = (const float*)d_in[3];
    const float* Whh  = (const float*)d_in[4];
    const float* bih  = (const float*)d_in[5];
    const float* bhh  = (const float*)d_in[6];
    const float* Wmlp = (const float*)d_in[7];
    const float* bmlp = (const float*)d_in[8];
    float* out = (float*)d_out;

    cudaFuncSetAttribute(lstm_hmma_kernel,
                         cudaFuncAttributeMaxDynamicSharedMemorySize, SM_TOTAL);
    lstm_hmma_kernel<<<NCTA, NTH, SM_TOTAL>>>(
        x, hx0, cx0, Wih, Whh, bih, bhh, Wmlp, bmlp, out);
}